// round 10
// baseline (speedup 1.0000x reference)
#include <cuda_runtime.h>
#include <cuda_fp16.h>
#include <math.h>

#define BATCH 32
#define H 512
#define W 512
#define HW (H*W)
#define NTOT (BATCH*HW)
#define KK_INV (1.0f/961.0f)

#define COLS_PB 256
#define ROWS_PB 32
#define NSLOT 36
#define NWARP 4
#define NTHR 128
#define NBLKX (W / COLS_PB)                 // 2
#define NBLKY (H / ROWS_PB)                 // 16
#define NBLK (BATCH * NBLKX * NBLKY)        // 1024
#define CHUNKS_PER_IMG (NBLKX * NBLKY)      // 32

// smem: fp16 ring (36 x 256) + reduction scratch
#define CB_BYTES   (NSLOT * COLS_PB * 2)    // 18432
#define RED_BYTES  (4 * NTHR * 4)           // 2048
#define SMEM_TOTAL (CB_BYTES + RED_BYTES)   // 20480

__device__ float g_part[NBLK][4];           // {bce, wsum, inter, union}
__device__ unsigned g_done = 0;

__device__ __forceinline__ int slotof(int row) {
    return (unsigned)(row + 72) % NSLOT;
}

// ---------------------------------------------------------------------------
// Warp computes the 31-wide horizontal box sum of one targ row restricted to
// global cols [X0, X0+255], writing fp16 into a 256-wide ring row.
// Pure-shuffle prefix pipeline over 10 chunks of 32 starting at gx0 = X0-32;
// out-of-image loads are zero, which makes all boundary clamping automatic.
// Output chunk m (=c-1, ring chunk c-2):  out[x] = P[x+15] - P[x-16].
// ---------------------------------------------------------------------------
__device__ __forceinline__ void produce_row(const float* __restrict__ tb, int row,
                                            int gx0, __half* __restrict__ cbrow,
                                            int lane) {
    if (row < 0 || row >= H) {
        #pragma unroll
        for (int m = 0; m < 8; ++m) cbrow[m * 32 + lane] = __float2half_rn(0.0f);
        return;
    }
    const unsigned FULL = 0xffffffffu;
    const float* __restrict__ rowp = tb + (size_t)row * W;

    float carry = 0.0f, Pprev = 0.0f, Pcur = 0.0f;
    #pragma unroll
    for (int c = 0; c < 10; ++c) {
        const int gc = gx0 + c * 32 + lane;
        float v = (gc >= 0 && gc < W) ? __ldg(rowp + gc) : 0.0f;
        #pragma unroll
        for (int off = 1; off < 32; off <<= 1) {
            float n = __shfl_up_sync(FULL, v, off);
            if (lane >= off) v += n;
        }
        const float Pnext = carry + v;
        carry += __shfl_sync(FULL, v, 31);

        if (c >= 2) {
            float a1 = __shfl_sync(FULL, Pcur,  (lane + 15) & 31);
            float a2 = __shfl_sync(FULL, Pnext, (lane - 17) & 31);
            float A  = (lane <= 16) ? a1 : a2;
            float b1 = __shfl_sync(FULL, Pcur,  (lane - 16) & 31);
            float b2 = __shfl_sync(FULL, Pprev, (lane + 16) & 31);
            float B  = (lane >= 16) ? b1 : b2;
            cbrow[(c - 2) * 32 + lane] = __float2half_rn(A - B);
        }
        Pprev = Pcur;
        Pcur  = Pnext;
    }
}

__device__ __forceinline__ void lane_math(float xv, float tv, float vsum,
                                          float& bce, float& ws, float& it, float& un) {
    const float w   = fmaf(5.0f, fabsf(vsum * KK_INV - tv), 1.0f);
    const float E   = __expf(-fabsf(xv));
    const float u   = 1.0f + E;
    const float sp  = fmaxf(xv, 0.0f) + __logf(u);
    const float inv = __fdividef(1.0f, u);
    const float p   = (xv >= 0.0f) ? inv : E * inv;
    bce += sp - xv * tv;
    ws  += w;
    it  += p * tv * w;
    un  += (p + tv) * w;
}

// ---------------------------------------------------------------------------
// Fused kernel: grid (2, 16, 32), block 128 (4 warps), 256-col x 32-row tiles.
// Groups of 4 rows: 4 warps produce 4 ring rows, 128 threads (2 cols each)
// consume. Last finished block performs global finalize.
// ---------------------------------------------------------------------------
extern __shared__ char smem_raw[];

__global__ __launch_bounds__(NTHR, 8)
void fused_kernel(const float* __restrict__ pred,
                  const float* __restrict__ targ,
                  float* __restrict__ out) {
    __half* CB  = (__half*)smem_raw;                  // [NSLOT][COLS_PB]
    float*  red = (float*)(smem_raw + CB_BYTES);      // [4][NTHR]

    const int b    = blockIdx.z;
    const int tid  = threadIdx.x;
    const int w    = tid >> 5;
    const int lane = tid & 31;
    const int X0   = blockIdx.x * COLS_PB;
    const int r0   = blockIdx.y * ROWS_PB;
    const int gx0  = X0 - 32;

    const float* __restrict__ tb = targ + (size_t)b * HW;
    const float* __restrict__ pb = pred + (size_t)b * HW;

    // Prologue: ring rows r0-15 .. r0+15 (31 rows, 4 warps, 8 rounds)
    #pragma unroll
    for (int k = 0; k < 8; ++k) {
        const int i = k * 4 + w;
        if (i < 31) {
            const int row = r0 - 15 + i;
            produce_row(tb, row, gx0, CB + slotof(row) * COLS_PB, lane);
        }
    }
    __syncthreads();

    // Initial vertical window (2 cols per thread: X0+2*tid, X0+2*tid+1)
    float vx = 0.f, vy = 0.f;
    #pragma unroll
    for (int i = 0; i < 31; ++i) {
        const int row = r0 - 15 + i;
        unsigned u = ((const unsigned*)(CB + slotof(row) * COLS_PB))[tid];
        float2 a = __half22float2(*reinterpret_cast<__half2*>(&u));
        vx += a.x; vy += a.y;
    }

    float bce_a = 0.f, wsum_a = 0.f, inter_a = 0.f, uni_a = 0.f;

    #pragma unroll
    for (int gr = 0; gr < ROWS_PB / 4; ++gr) {
        const int r = r0 + gr * 4;
        // Produce rows r+16 .. r+19, one per warp
        {
            const int row = r + 16 + w;
            produce_row(tb, row, gx0, CB + slotof(row) * COLS_PB, lane);
        }
        __syncthreads();

        #pragma unroll
        for (int j = 0; j < 4; ++j) {
            const int rr = r + j;
            const float2 tv = *(const float2*)(tb + (size_t)rr * W + X0 + 2 * tid);
            const float2 xv = *(const float2*)(pb + (size_t)rr * W + X0 + 2 * tid);

            lane_math(xv.x, tv.x, vx, bce_a, wsum_a, inter_a, uni_a);
            lane_math(xv.y, tv.y, vy, bce_a, wsum_a, inter_a, uni_a);

            // slide: add row rr+16, subtract row rr-15
            unsigned ua = ((const unsigned*)(CB + slotof(rr + 16) * COLS_PB))[tid];
            unsigned us = ((const unsigned*)(CB + slotof(rr - 15) * COLS_PB))[tid];
            float2 aa = __half22float2(*reinterpret_cast<__half2*>(&ua));
            float2 sa = __half22float2(*reinterpret_cast<__half2*>(&us));
            vx += aa.x - sa.x;
            vy += aa.y - sa.y;
        }
        __syncthreads();   // ring slots free before next produce
    }

    // Deterministic block reduction (fixed order)
    red[0 * NTHR + tid] = bce_a;
    red[1 * NTHR + tid] = wsum_a;
    red[2 * NTHR + tid] = inter_a;
    red[3 * NTHR + tid] = uni_a;
    __syncthreads();
    #pragma unroll
    for (int off = NTHR / 2; off > 0; off >>= 1) {
        if (tid < off) {
            red[0 * NTHR + tid] += red[0 * NTHR + tid + off];
            red[1 * NTHR + tid] += red[1 * NTHR + tid + off];
            red[2 * NTHR + tid] += red[2 * NTHR + tid + off];
            red[3 * NTHR + tid] += red[3 * NTHR + tid + off];
        }
        __syncthreads();
    }

    __shared__ unsigned last_flag;
    if (tid == 0) {
        const int blin = b * CHUNKS_PER_IMG + blockIdx.y * NBLKX + blockIdx.x;
        g_part[blin][0] = red[0 * NTHR];
        g_part[blin][1] = red[1 * NTHR];
        g_part[blin][2] = red[2 * NTHR];
        g_part[blin][3] = red[3 * NTHR];
        __threadfence();
        last_flag = (atomicAdd(&g_done, 1u) == NBLK - 1u);
    }
    __syncthreads();
    if (!last_flag) return;

    // ---- Last block: global finalize (fixed-order sums) ----
    __threadfence();
    if (tid == 0) g_done = 0;   // reset for next graph replay

    float acc = 0.0f;
    #pragma unroll
    for (int j = 0; j < NBLK / NTHR; ++j) acc += g_part[tid * (NBLK / NTHR) + j][0];
    red[tid] = acc;
    __syncthreads();
    #pragma unroll
    for (int off = NTHR / 2; off > 0; off >>= 1) {
        if (tid < off) red[tid] += red[tid + off];
        __syncthreads();
    }
    const float bce = red[0] * (1.0f / (float)NTOT);
    __syncthreads();

    if (tid < BATCH) {
        float ws = 0.0f, it = 0.0f, un = 0.0f;
        #pragma unroll
        for (int j = 0; j < CHUNKS_PER_IMG; ++j) {
            const int bl = tid * CHUNKS_PER_IMG + j;
            ws += g_part[bl][1];
            it += g_part[bl][2];
            un += g_part[bl][3];
        }
        const float w_bce = (ws * bce + 1e-8f) / (ws + 1e-8f);
        const float w_iou = 1.0f - (it + 1.0f + 1e-8f) / (un - it + 1.0f + 1e-8f);
        red[tid] = w_bce + w_iou;
    }
    __syncthreads();
    if (tid == 0) {
        float a = 0.0f;
        #pragma unroll
        for (int i = 0; i < BATCH; ++i) a += red[i];
        out[0] = a * (1.0f / (float)BATCH);
    }
}

// ---------------------------------------------------------------------------
extern "C" void kernel_launch(void* const* d_in, const int* in_sizes, int n_in,
                              void* d_out, int out_size) {
    const float* y_pred   = (const float*)d_in[0];
    const float* y_target = (const float*)d_in[1];
    float* out = (float*)d_out;

    cudaFuncSetAttribute(fused_kernel, cudaFuncAttributeMaxDynamicSharedMemorySize,
                         SMEM_TOTAL);

    dim3 g(NBLKX, NBLKY, BATCH);      // (2, 16, 32) = 1024 blocks
    fused_kernel<<<g, NTHR, SMEM_TOTAL>>>(y_pred, y_target, out);
}

// round 11
// speedup vs baseline: 1.3689x; 1.3689x over previous
#include <cuda_runtime.h>
#include <cuda_fp16.h>
#include <math.h>

#define BATCH 32
#define H 512
#define W 512
#define HW (H*W)
#define NTOT (BATCH*HW)
#define KK_INV (1.0f/961.0f)

#define ROWS_PB 32
#define NSLOT 48
#define NTHR 256
#define NBLKY (H / ROWS_PB)                 // 16
#define NBLK (BATCH * NBLKY)                // 512
#define CHUNKS_PER_IMG NBLKY                // 16

#define CB_BYTES   (NSLOT * W * 2)          // 49152
#define RED_BYTES  (4 * 128 * 4)            // 2048
#define SMEM_TOTAL (CB_BYTES + RED_BYTES)   // 51200

__device__ float g_part[NBLK][4];           // {bce, wsum, inter, union}
__device__ unsigned g_done = 0;

__device__ __forceinline__ int slotof(int row) {
    return (unsigned)(row + 48) % NSLOT;    // row >= -15 always
}

// Emit output chunk m (32 quads): out[x] = P[x+15] - P[x-16], using prefix
// quads of chunks m-1 (Qp), m (Qc), m+1 (Qn). 16 shuffles per 128 elems.
__device__ __forceinline__ void emit_chunk(uint2* __restrict__ cb2, int m,
                                           float4 Qp, float4 Qc, float4 Qn,
                                           int lane) {
    const unsigned FULL = 0xffffffffu;
    const int lp3 = (lane + 3) & 31;
    const int lp4 = (lane + 4) & 31;
    const int lm4 = (lane - 4) & 31;

    float axm = __shfl_sync(FULL, Qc.w, lp3), axn = __shfl_sync(FULL, Qn.w, lp3);
    float aym = __shfl_sync(FULL, Qc.x, lp4), ayn = __shfl_sync(FULL, Qn.x, lp4);
    float azm = __shfl_sync(FULL, Qc.y, lp4), azn = __shfl_sync(FULL, Qn.y, lp4);
    float awm = __shfl_sync(FULL, Qc.z, lp4), awn = __shfl_sync(FULL, Qn.z, lp4);
    float Ax = (lane <= 28) ? axm : axn;
    float Ay = (lane <= 27) ? aym : ayn;
    float Az = (lane <= 27) ? azm : azn;
    float Aw = (lane <= 27) ? awm : awn;

    float bxm = __shfl_sync(FULL, Qc.x, lm4), bxp = __shfl_sync(FULL, Qp.x, lm4);
    float bym = __shfl_sync(FULL, Qc.y, lm4), byp = __shfl_sync(FULL, Qp.y, lm4);
    float bzm = __shfl_sync(FULL, Qc.z, lm4), bzp = __shfl_sync(FULL, Qp.z, lm4);
    float bwm = __shfl_sync(FULL, Qc.w, lm4), bwp = __shfl_sync(FULL, Qp.w, lm4);
    float Bx = (lane >= 4) ? bxm : bxp;
    float By = (lane >= 4) ? bym : byp;
    float Bz = (lane >= 4) ? bzm : bzp;
    float Bw = (lane >= 4) ? bwm : bwp;

    __half2 h0 = __floats2half2_rn(Ax - Bx, Ay - By);
    __half2 h1 = __floats2half2_rn(Az - Bz, Aw - Bw);
    uint2 u;
    u.x = *reinterpret_cast<unsigned*>(&h0);
    u.y = *reinterpret_cast<unsigned*>(&h1);
    cb2[m * 32 + lane] = u;
}

// Warp computes the 31-wide horizontal box sum of one full targ row into an
// fp16 ring row. Pure-register quad pipeline; no smem scratch.
__device__ __forceinline__ void produce_row(const float* __restrict__ tb, int row,
                                            __half* __restrict__ cbrow, int lane) {
    uint2* cb2 = (uint2*)cbrow;
    if (row < 0 || row >= H) {
        #pragma unroll
        for (int c = 0; c < 4; ++c) cb2[c * 32 + lane] = make_uint2(0u, 0u);
        return;
    }
    const unsigned FULL = 0xffffffffu;
    const float4* __restrict__ rowp = (const float4*)(tb + (size_t)row * W);

    float carry = 0.0f;
    float4 Qa = make_float4(0.f, 0.f, 0.f, 0.f);   // chunk c-2 prefix quads
    float4 Qb = make_float4(0.f, 0.f, 0.f, 0.f);   // chunk c-1 prefix quads

    #pragma unroll
    for (int c = 0; c < 4; ++c) {
        float4 q = rowp[c * 32 + lane];
        float p0 = q.x;
        float p1 = p0 + q.y;
        float p2 = p1 + q.z;
        float p3 = p2 + q.w;
        float s = p3;
        #pragma unroll
        for (int off = 1; off < 32; off <<= 1) {
            float n = __shfl_up_sync(FULL, s, off);
            if (lane >= off) s += n;
        }
        const float base = s - p3 + carry;
        float4 Qc = make_float4(base + p0, base + p1, base + p2, base + p3);
        carry += __shfl_sync(FULL, s, 31);

        if (c >= 1) emit_chunk(cb2, c - 1, Qa, Qb, Qc, lane);
        Qa = Qb;
        Qb = Qc;
    }
    // last chunk: P beyond col 511 equals the row total
    float4 Qt = make_float4(carry, carry, carry, carry);
    emit_chunk(cb2, 3, Qa, Qb, Qt, lane);
}

__device__ __forceinline__ void lane_math(float xv, float tv, float vsum,
                                          float& bce, float& ws, float& it, float& un) {
    const float w   = fmaf(5.0f, fabsf(vsum * KK_INV - tv), 1.0f);
    const float E   = __expf(-fabsf(xv));
    const float u   = 1.0f + E;
    const float sp  = fmaxf(xv, 0.0f) + __logf(u);
    const float inv = __fdividef(1.0f, u);
    const float p   = (xv >= 0.0f) ? inv : E * inv;
    bce += sp - xv * tv;
    ws  += w;
    it  += p * tv * w;
    un  += (p + tv) * w;
}

// ---------------------------------------------------------------------------
// Warp-specialized fused kernel: grid (16, 32), block 256.
// Warps 0-3 produce fp16 hsum ring rows; warps 4-7 (128 threads, 4 cols each)
// run the vertical sliding-window + loss math. 40-row prologue by all 8 warps.
// Last finished block performs the global finalize.
// ---------------------------------------------------------------------------
extern __shared__ char smem_raw[];

__global__ __launch_bounds__(NTHR, 4)
void fused_kernel(const float* __restrict__ pred,
                  const float* __restrict__ targ,
                  float* __restrict__ out) {
    __half* CB  = (__half*)smem_raw;                 // [NSLOT][W]
    float*  red = (float*)(smem_raw + CB_BYTES);     // [4][128]

    const int b    = blockIdx.y;
    const int tid  = threadIdx.x;
    const int wid  = tid >> 5;
    const int lane = tid & 31;
    const int r0   = blockIdx.x * ROWS_PB;

    const float* __restrict__ tb = targ + (size_t)b * HW;
    const float* __restrict__ pb = pred + (size_t)b * HW;
    const float4* __restrict__ tb4 = (const float4*)tb;
    const float4* __restrict__ pb4 = (const float4*)pb;

    // Prologue: all 8 warps produce ring rows r0-15 .. r0+24 (40 rows)
    #pragma unroll
    for (int k = 0; k < 5; ++k) {
        const int row = r0 - 15 + k * 8 + wid;
        produce_row(tb, row, CB + slotof(row) * W, lane);
    }
    __syncthreads();

    float vx = 0.f, vy = 0.f, vz = 0.f, vw = 0.f;
    float bce_a = 0.f, wsum_a = 0.f, inter_a = 0.f, uni_a = 0.f;
    const int ct = tid - 128;                         // consumer float4-col index

    #pragma unroll
    for (int s = 0; s < 4; ++s) {
        if (tid < 128) {
            // Producers: rows r0+25+8s .. r0+32+8s (guarded to <= r0+47)
            if (s < 3) {
                const int base = r0 + 25 + 8 * s;
                const int row1 = base + wid;
                const int row2 = base + 4 + wid;
                produce_row(tb, row1, CB + slotof(row1) * W, lane);
                if (row2 <= r0 + 47)
                    produce_row(tb, row2, CB + slotof(row2) * W, lane);
            }
        } else {
            if (s == 0) {
                // Initial vertical window: rows r0-15 .. r0+15
                #pragma unroll
                for (int i = 0; i < 31; ++i) {
                    const int row = r0 - 15 + i;
                    uint2 u = ((const uint2*)(CB + slotof(row) * W))[ct];
                    float2 a = __half22float2(*reinterpret_cast<__half2*>(&u.x));
                    float2 c = __half22float2(*reinterpret_cast<__half2*>(&u.y));
                    vx += a.x; vy += a.y; vz += c.x; vw += c.y;
                }
            }
            // Consume 8 output rows
            #pragma unroll
            for (int j = 0; j < 8; ++j) {
                const int rr = r0 + 8 * s + j;
                const float4 tv = tb4[rr * (W/4) + ct];
                const float4 xv = pb4[rr * (W/4) + ct];

                lane_math(xv.x, tv.x, vx, bce_a, wsum_a, inter_a, uni_a);
                lane_math(xv.y, tv.y, vy, bce_a, wsum_a, inter_a, uni_a);
                lane_math(xv.z, tv.z, vz, bce_a, wsum_a, inter_a, uni_a);
                lane_math(xv.w, tv.w, vw, bce_a, wsum_a, inter_a, uni_a);

                // slide: add row rr+16, subtract row rr-15
                uint2 ua = ((const uint2*)(CB + slotof(rr + 16) * W))[ct];
                uint2 us = ((const uint2*)(CB + slotof(rr - 15) * W))[ct];
                float2 aa = __half22float2(*reinterpret_cast<__half2*>(&ua.x));
                float2 ab = __half22float2(*reinterpret_cast<__half2*>(&ua.y));
                float2 sa = __half22float2(*reinterpret_cast<__half2*>(&us.x));
                float2 sb = __half22float2(*reinterpret_cast<__half2*>(&us.y));
                vx += aa.x - sa.x;
                vy += aa.y - sa.y;
                vz += ab.x - sb.x;
                vw += ab.y - sb.y;
            }
        }
        __syncthreads();
    }

    // Consumers write partials; deterministic tree over 128 entries.
    if (tid >= 128) {
        red[0 * 128 + ct] = bce_a;
        red[1 * 128 + ct] = wsum_a;
        red[2 * 128 + ct] = inter_a;
        red[3 * 128 + ct] = uni_a;
    }
    __syncthreads();
    #pragma unroll
    for (int off = 64; off > 0; off >>= 1) {
        if (tid < off) {
            red[0 * 128 + tid] += red[0 * 128 + tid + off];
            red[1 * 128 + tid] += red[1 * 128 + tid + off];
            red[2 * 128 + tid] += red[2 * 128 + tid + off];
            red[3 * 128 + tid] += red[3 * 128 + tid + off];
        }
        __syncthreads();
    }

    __shared__ unsigned last_flag;
    if (tid == 0) {
        const int blin = b * CHUNKS_PER_IMG + blockIdx.x;
        g_part[blin][0] = red[0 * 128];
        g_part[blin][1] = red[1 * 128];
        g_part[blin][2] = red[2 * 128];
        g_part[blin][3] = red[3 * 128];
        __threadfence();
        last_flag = (atomicAdd(&g_done, 1u) == NBLK - 1u);
    }
    __syncthreads();
    if (!last_flag) return;

    // ---- Last block: global finalize (fixed-order sums) ----
    __threadfence();
    if (tid == 0) g_done = 0;    // reset for next graph replay

    float acc = 0.0f;
    #pragma unroll
    for (int j = 0; j < NBLK / NTHR; ++j) acc += g_part[tid * (NBLK / NTHR) + j][0];
    red[tid] = acc;
    __syncthreads();
    #pragma unroll
    for (int off = NTHR / 2; off > 0; off >>= 1) {
        if (tid < off) red[tid] += red[tid + off];
        __syncthreads();
    }
    const float bce = red[0] * (1.0f / (float)NTOT);
    __syncthreads();

    if (tid < BATCH) {
        float ws = 0.0f, it = 0.0f, un = 0.0f;
        #pragma unroll
        for (int j = 0; j < CHUNKS_PER_IMG; ++j) {
            const int bl = tid * CHUNKS_PER_IMG + j;
            ws += g_part[bl][1];
            it += g_part[bl][2];
            un += g_part[bl][3];
        }
        const float w_bce = (ws * bce + 1e-8f) / (ws + 1e-8f);
        const float w_iou = 1.0f - (it + 1.0f + 1e-8f) / (un - it + 1.0f + 1e-8f);
        red[tid] = w_bce + w_iou;
    }
    __syncthreads();
    if (tid == 0) {
        float a = 0.0f;
        #pragma unroll
        for (int i = 0; i < BATCH; ++i) a += red[i];
        out[0] = a * (1.0f / (float)BATCH);
    }
}

// ---------------------------------------------------------------------------
extern "C" void kernel_launch(void* const* d_in, const int* in_sizes, int n_in,
                              void* d_out, int out_size) {
    const float* y_pred   = (const float*)d_in[0];
    const float* y_target = (const float*)d_in[1];
    float* out = (float*)d_out;

    cudaFuncSetAttribute(fused_kernel, cudaFuncAttributeMaxDynamicSharedMemorySize,
                         SMEM_TOTAL);

    dim3 g(NBLKY, BATCH);             // (16, 32) = 512 blocks
    fused_kernel<<<g, NTHR, SMEM_TOTAL>>>(y_pred, y_target, out);
}